// round 2
// baseline (speedup 1.0000x reference)
#include <cuda_runtime.h>

// RCNNTargetGenerator: faster-rcnn bbox target encoding, elementwise over N=2M rows.
//
// Inputs (metadata order):
//   d_in[0] gt_rois  float32 [1,N,5]  (x1,y1,x2,y2,cls)
//   d_in[1] rois     float32 [1,N,5]  (batch, x1,y1,x2,y2)
//   d_in[2] labels   int32   [N]   (JAX x64 disabled -> int64 request materializes int32)
//   d_in[3] means    float32 [4]
//   d_in[4] stds     float32 [4]
//   d_in[5] inside_w float32 [4]
// Output: float32, 3 * N * 4 elements, concatenated:
//   [0      , N*4)   bbox_targets
//   [N*4    , 2*N*4) bbox_inside_weights
//   [2*N*4  , 3*N*4) bbox_outside_weights

__global__ __launch_bounds__(256) void rcnn_target_kernel(
    const float* __restrict__ gt,      // [N,5]
    const float* __restrict__ rois,    // [N,5]
    const int*   __restrict__ labels,  // [N]
    const float* __restrict__ means,
    const float* __restrict__ stds,
    const float* __restrict__ iw,
    float* __restrict__ out_t,         // [N,4]
    float* __restrict__ out_in,        // [N,4]
    float* __restrict__ out_out,       // [N,4]
    int n)
{
    int i = blockIdx.x * blockDim.x + threadIdx.x;
    if (i >= n) return;

    // broadcast constants (L1-resident)
    float m0 = __ldg(means + 0), m1 = __ldg(means + 1),
          m2 = __ldg(means + 2), m3 = __ldg(means + 3);
    float s0 = __ldg(stds + 0), s1 = __ldg(stds + 1),
          s2 = __ldg(stds + 2), s3 = __ldg(stds + 3);
    float w0 = __ldg(iw + 0), w1 = __ldg(iw + 1),
          w2 = __ldg(iw + 2), w3 = __ldg(iw + 3);

    // per-row loads (stride-5 rows; coalesced in aggregate across the warp)
    const float* r = rois + (size_t)i * 5;
    float ex_x1 = __ldg(r + 1);
    float ex_y1 = __ldg(r + 2);
    float ex_x2 = __ldg(r + 3);
    float ex_y2 = __ldg(r + 4);

    const float* g = gt + (size_t)i * 5;
    float gt_x1 = __ldg(g + 0);
    float gt_y1 = __ldg(g + 1);
    float gt_x2 = __ldg(g + 2);
    float gt_y2 = __ldg(g + 3);

    bool pos = __ldg(labels + i) > 0;

    // delta encoding
    float ex_w  = ex_x2 - ex_x1 + 1.0f;
    float ex_h  = ex_y2 - ex_y1 + 1.0f;
    float ex_cx = ex_x1 + 0.5f * ex_w;
    float ex_cy = ex_y1 + 0.5f * ex_h;
    float gt_w  = gt_x2 - gt_x1 + 1.0f;
    float gt_h  = gt_y2 - gt_y1 + 1.0f;
    float gt_cx = gt_x1 + 0.5f * gt_w;
    float gt_cy = gt_y1 + 0.5f * gt_h;

    float dx = __fdividef(gt_cx - ex_cx, ex_w);
    float dy = __fdividef(gt_cy - ex_cy, ex_h);
    float dw = __logf(__fdividef(gt_w, ex_w));
    float dh = __logf(__fdividef(gt_h, ex_h));

    // normalize
    dx = __fdividef(dx - m0, s0);
    dy = __fdividef(dy - m1, s1);
    dw = __fdividef(dw - m2, s2);
    dh = __fdividef(dh - m3, s3);

    float4 t4, i4, o4;
    if (pos) {
        t4 = make_float4(dx, dy, dw, dh);
        i4 = make_float4(w0, w1, w2, w3);
        o4 = make_float4(w0 > 0.0f ? 1.0f : 0.0f,
                         w1 > 0.0f ? 1.0f : 0.0f,
                         w2 > 0.0f ? 1.0f : 0.0f,
                         w3 > 0.0f ? 1.0f : 0.0f);
    } else {
        t4 = make_float4(0.0f, 0.0f, 0.0f, 0.0f);
        i4 = t4;
        o4 = t4;
    }

    reinterpret_cast<float4*>(out_t)[i]   = t4;
    reinterpret_cast<float4*>(out_in)[i]  = i4;
    reinterpret_cast<float4*>(out_out)[i] = o4;
}

extern "C" void kernel_launch(void* const* d_in, const int* in_sizes, int n_in,
                              void* d_out, int out_size)
{
    const float* gt     = (const float*)d_in[0];
    const float* rois   = (const float*)d_in[1];
    const int*   labels = (const int*)d_in[2];
    const float* means  = (const float*)d_in[3];
    const float* stds   = (const float*)d_in[4];
    const float* iw     = (const float*)d_in[5];

    int n = in_sizes[0] / 5;        // gt_rois is [1,N,5] -> dtype-independent N
    float* out = (float*)d_out;
    float* out_t   = out;
    float* out_in  = out + (size_t)n * 4;
    float* out_out = out + (size_t)n * 8;

    int threads = 256;
    int blocks = (n + threads - 1) / threads;
    rcnn_target_kernel<<<blocks, threads>>>(gt, rois, labels, means, stds, iw,
                                            out_t, out_in, out_out, n);
}